// round 8
// baseline (speedup 1.0000x reference)
#include <cuda_runtime.h>
#include <float.h>
#include <math.h>

// SpectoCapsLayer: capsule routing, register-resident u, octet-coalesced W.
//   x: [B=256, I=1152, F=8] fp32
//   W: [I=1152, O=10, F=8, G=16] fp32
//   u[b,i,o,g] = sum_f x[b,i,f] * W[i,o,f,g]
//   3 routing steps; logits_t = u . (sum of previous v's)  (closed form)
//   out = [ v3: (B,O,G) 40960 floats | u: (B,I,O,G) 47185920 floats ]
//
// Mapping: 512 threads = 64 octets (8 lanes). Octet owns 18 i's (interleaved
// within the warp: i = 72*warp + octw + 4k). Per i the octet loads the full
// 512-B W chunk as 4x contiguous 128-B LDG.128 (lane l -> f=2j+(l>>2), g-slice
// l&3). Each lane accumulates BOTH batches' partials over its f-half; one
// shfl_xor(4) exchange completes u: lanes l<4 keep b0, lanes l>=4 keep b1.
// W is thus read once per CTA (shared across the b-pair), fully coalesced.
// Routing dots complete with 2 quad shuffles; softmax needs no max-subtraction
// (|logit| <~ 25, exp safe in fp32).

#define TPB 512
#define B_DIM 256
#define I_DIM 1152
#define O_DIM 10
#define F_DIM 8
#define G_DIM 16
#define BTILE 2
#define IPT 18                            // i's per octet

// static shared: scratch(2048) + wred(32) + small(128)
#define SCRATCH_OFF 0
#define WRED_OFF    2048
#define SMALL_OFF   2080
#define SM_TOTAL    2208

// small-region indices
#define SM_VSUM 0   // [2][16] running sum of v's
#define SM_Z    64  // Z0, Z1

__device__ __forceinline__ void block_reduce2_sum(float v0, float v1, float* wred,
                                                  float* small, int tid) {
    const unsigned FULL = 0xffffffffu;
    #pragma unroll
    for (int off = 16; off > 0; off >>= 1) {
        v0 += __shfl_xor_sync(FULL, v0, off);
        v1 += __shfl_xor_sync(FULL, v1, off);
    }
    int lane = tid & 31, wid = tid >> 5;
    if (lane == 0) { wred[wid * 2] = v0; wred[wid * 2 + 1] = v1; }
    __syncthreads();
    if (tid == 0) {
        float a0 = wred[0], a1 = wred[1];
        #pragma unroll
        for (int w = 1; w < TPB / 32; w++) {
            a0 += wred[w * 2];
            a1 += wred[w * 2 + 1];
        }
        small[SM_Z] = a0; small[SM_Z + 1] = a1;
    }
    __syncthreads();
}

// Reduce 128-group partials -> s[2][16], scale by invZ, squash, accumulate Vsum.
__device__ __forceinline__ void finish_step(float* scratch, float* small, int tid,
                                            float invZ0, float invZ1,
                                            bool write_out, float* out_v,
                                            int b_base, int o) {
    if (tid < 32) {
        int b = tid >> 4, g = tid & 15;
        float s = 0.f;
        const float* sc = scratch + (b * 64) * 16 + g;
        #pragma unroll 8
        for (int grp = 0; grp < 64; grp++) s += sc[grp * 16];
        s *= (b ? invZ1 : invZ0);
        // squash: v = s * n / (n^2 + 1), n = ||s|| over g (16 lanes)
        float sq = s * s;
        #pragma unroll
        for (int off = 8; off > 0; off >>= 1)
            sq += __shfl_xor_sync(0xffffffffu, sq, off);   // stays in 16-lane half
        float n = sqrtf(sq);
        float fac = n / (sq + 1.0f);
        float v = s * fac;
        small[SM_VSUM + tid] += v;
        if (write_out)
            out_v[((b_base + b) * O_DIM + o) * G_DIM + g] = v;
    }
    __syncthreads();
}

__global__ void __launch_bounds__(TPB, 1)
caps_kernel(const float* __restrict__ x, const float* __restrict__ W,
            float* __restrict__ out_v, float* __restrict__ out_u) {
    __shared__ float sm[SM_TOTAL];
    float* scratch = sm + SCRATCH_OFF;   // 2048 floats (128 groups x 16)
    float* wred    = sm + WRED_OFF;      // 32 floats
    float* small   = sm + SMALL_OFF;     // 128 floats

    const int tid = threadIdx.x;
    const int o = blockIdx.y;
    const int b_base = blockIdx.x * BTILE;

    const int lane = tid & 31;
    const int warp = tid >> 5;
    const int octw = lane >> 3;          // octet within warp 0..3
    const int l    = lane & 7;           // lane within octet
    const int q    = l & 3;              // g-slice [4q,4q+4)
    const int half = l >> 2;             // 0 -> keeps b0, 1 -> keeps b1; f-parity
    const int ot   = warp * 4 + octw;    // global octet 0..63
    const int group = half * 64 + ot;    // scratch partition (b-major)

    if (tid < 32) small[SM_VSUM + tid] = 0.f;
    __syncthreads();

    const unsigned FULL = 0xffffffffu;
    float4 u[IPT];

    // ---- phase 1: compute u into registers, store to gmem, uniform-weight sums ----
    {
        float a0 = 0.f, a1 = 0.f, a2 = 0.f, a3 = 0.f;
        const float4* Wv = reinterpret_cast<const float4*>(W);
        #pragma unroll 2
        for (int k = 0; k < IPT; k++) {
            const int i = warp * 72 + octw + 4 * k;
            // x rows for both batches (32 B each, broadcast across octet)
            const float4* x0p = reinterpret_cast<const float4*>(
                x + ((size_t)b_base * I_DIM + i) * F_DIM);
            const float4* x1p = reinterpret_cast<const float4*>(
                x + ((size_t)(b_base + 1) * I_DIM + i) * F_DIM);
            float4 x0a = x0p[0], x0b = x0p[1];
            float4 x1a = x1p[0], x1b = x1p[1];
            // this lane's f-set is {2j + half}: select parity-half of each row
            float4 X0 = half ? make_float4(x0a.y, x0a.w, x0b.y, x0b.w)
                             : make_float4(x0a.x, x0a.z, x0b.x, x0b.z);
            float4 X1 = half ? make_float4(x1a.y, x1a.w, x1b.y, x1b.w)
                             : make_float4(x1a.x, x1a.z, x1b.x, x1b.z);

            // W chunk for (i,o): 512 B; octet reads 4x128B contiguous.
            const float4* wb = Wv + (size_t)(i * O_DIM + o) * 32 + l;
            float4 acc0 = make_float4(0.f, 0.f, 0.f, 0.f);
            float4 acc1 = make_float4(0.f, 0.f, 0.f, 0.f);
            {
                float4 w = wb[0];                  // f = 0+half
                acc0.x = fmaf(X0.x, w.x, acc0.x); acc0.y = fmaf(X0.x, w.y, acc0.y);
                acc0.z = fmaf(X0.x, w.z, acc0.z); acc0.w = fmaf(X0.x, w.w, acc0.w);
                acc1.x = fmaf(X1.x, w.x, acc1.x); acc1.y = fmaf(X1.x, w.y, acc1.y);
                acc1.z = fmaf(X1.x, w.z, acc1.z); acc1.w = fmaf(X1.x, w.w, acc1.w);
            }
            {
                float4 w = wb[8];                  // f = 2+half
                acc0.x = fmaf(X0.y, w.x, acc0.x); acc0.y = fmaf(X0.y, w.y, acc0.y);
                acc0.z = fmaf(X0.y, w.z, acc0.z); acc0.w = fmaf(X0.y, w.w, acc0.w);
                acc1.x = fmaf(X1.y, w.x, acc1.x); acc1.y = fmaf(X1.y, w.y, acc1.y);
                acc1.z = fmaf(X1.y, w.z, acc1.z); acc1.w = fmaf(X1.y, w.w, acc1.w);
            }
            {
                float4 w = wb[16];                 // f = 4+half
                acc0.x = fmaf(X0.z, w.x, acc0.x); acc0.y = fmaf(X0.z, w.y, acc0.y);
                acc0.z = fmaf(X0.z, w.z, acc0.z); acc0.w = fmaf(X0.z, w.w, acc0.w);
                acc1.x = fmaf(X1.z, w.x, acc1.x); acc1.y = fmaf(X1.z, w.y, acc1.y);
                acc1.z = fmaf(X1.z, w.z, acc1.z); acc1.w = fmaf(X1.z, w.w, acc1.w);
            }
            {
                float4 w = wb[24];                 // f = 6+half
                acc0.x = fmaf(X0.w, w.x, acc0.x); acc0.y = fmaf(X0.w, w.y, acc0.y);
                acc0.z = fmaf(X0.w, w.z, acc0.z); acc0.w = fmaf(X0.w, w.w, acc0.w);
                acc1.x = fmaf(X1.w, w.x, acc1.x); acc1.y = fmaf(X1.w, w.y, acc1.y);
                acc1.z = fmaf(X1.w, w.z, acc1.z); acc1.w = fmaf(X1.w, w.w, acc1.w);
            }
            // exchange complementary f-half: lane keeps b = half.
            // send the partial for the OTHER lane's b; receive ours.
            float4 send = half ? acc0 : acc1;
            send.x = __shfl_xor_sync(FULL, send.x, 4);
            send.y = __shfl_xor_sync(FULL, send.y, 4);
            send.z = __shfl_xor_sync(FULL, send.z, 4);
            send.w = __shfl_xor_sync(FULL, send.w, 4);
            float4 mine = half ? acc1 : acc0;
            float4 r = make_float4(mine.x + send.x, mine.y + send.y,
                                   mine.z + send.z, mine.w + send.w);
            u[k] = r;
            float* gp = out_u +
                ((((size_t)(b_base + half) * I_DIM + i) * O_DIM + o) << 4);
            reinterpret_cast<float4*>(gp)[q] = r;
            a0 += r.x; a1 += r.y; a2 += r.z; a3 += r.w;
        }
        float* scr = scratch + group * 16 + q * 4;
        scr[0] = a0; scr[1] = a1; scr[2] = a2; scr[3] = a3;
        __syncthreads();
    }

    // step 1: uniform coefficients -> mean over i
    finish_step(scratch, small, tid, 1.0f / I_DIM, 1.0f / I_DIM,
                false, out_v, b_base, o);

    // ---- routing steps 2 and 3 (all register-resident) ----
    #pragma unroll 1
    for (int step = 1; step < 3; step++) {
        // per-i dot with Vsum (quad-completed), exp, partial Z
        float4 V = reinterpret_cast<const float4*>(small + SM_VSUM + half * G_DIM)[q];
        float e[IPT];
        float pz = 0.f;
        #pragma unroll
        for (int k = 0; k < IPT; k++) {
            float d = u[k].x * V.x + u[k].y * V.y + u[k].z * V.z + u[k].w * V.w;
            d += __shfl_xor_sync(FULL, d, 1);
            d += __shfl_xor_sync(FULL, d, 2);     // full 16-g dot within quad
            float ev = __expf(d);                 // |d| <~ 25, safe in fp32
            e[k] = ev;
            pz += ev;
        }
        // Z per b (each (b,i) counted by its 4 quad lanes -> x4)
        block_reduce2_sum(half ? 0.f : pz, half ? pz : 0.f, wred, small, tid);
        float invZ0 = 4.0f / small[SM_Z];
        float invZ1 = 4.0f / small[SM_Z + 1];

        // weighted accumulation from registers
        float a0 = 0.f, a1 = 0.f, a2 = 0.f, a3 = 0.f;
        #pragma unroll
        for (int k = 0; k < IPT; k++) {
            float ev = e[k];
            a0 = fmaf(ev, u[k].x, a0);
            a1 = fmaf(ev, u[k].y, a1);
            a2 = fmaf(ev, u[k].z, a2);
            a3 = fmaf(ev, u[k].w, a3);
        }
        float* scr = scratch + group * 16 + q * 4;
        scr[0] = a0; scr[1] = a1; scr[2] = a2; scr[3] = a3;
        __syncthreads();

        finish_step(scratch, small, tid, invZ0, invZ1,
                    (step == 2), out_v, b_base, o);
    }
}

extern "C" void kernel_launch(void* const* d_in, const int* in_sizes, int n_in,
                              void* d_out, int out_size) {
    const float* x = (const float*)d_in[0];   // [256,1152,8]
    const float* W = (const float*)d_in[1];   // [1152,10,8,16]
    float* out = (float*)d_out;
    float* out_v = out;                         // [256,10,16] = 40960
    float* out_u = out + B_DIM * O_DIM * G_DIM; // [256,1152,10,16]

    dim3 grid(B_DIM / BTILE, O_DIM);
    caps_kernel<<<grid, TPB>>>(x, W, out_v, out_u);
}

// round 10
// speedup vs baseline: 1.4256x; 1.4256x over previous
#include <cuda_runtime.h>
#include <float.h>
#include <math.h>

// SpectoCapsLayer: capsule routing, register-resident u, octet-coalesced W,
// strength-reduced addressing.
//   x: [B=256, I=1152, F=8] fp32
//   W: [I=1152, O=10, F=8, G=16] fp32
//   u[b,i,o,g] = sum_f x[b,i,f] * W[i,o,f,g]
//   3 routing steps; logits_t = u . (sum of previous v's)  (closed form)
//   out = [ v3: (B,O,G) 40960 floats | u: (B,I,O,G) 47185920 floats ]
//
// Mapping: 512 threads = 64 octets (8 lanes). Octet owns 18 i's (interleaved:
// i = 72*warp + octw + 4k). Per i the octet loads the 512-B W chunk as 4x
// contiguous 128-B LDG.128 (lane l -> f=2j+(l>>2), g-slice l&3). Lane
// accumulates BOTH batches over its f-half; shfl_xor(4) exchange completes u:
// lanes l<4 keep b0, l>=4 keep b1. W read once per CTA.
// All loop addresses are induction pointers (constant strides); x f-halves
// read as stride-2 scalar loads (no selects).

#define TPB 512
#define B_DIM 256
#define I_DIM 1152
#define O_DIM 10
#define F_DIM 8
#define G_DIM 16
#define BTILE 2
#define IPT 18                            // i's per octet

// strides per k (i advances by 4)
#define W_STRIDE_V4  (4 * O_DIM * 32)     // 1280 float4
#define X_STRIDE_F   (4 * F_DIM)          // 32 floats
#define U_STRIDE_V4  (4 * O_DIM * 4)      // 160 float4

// static shared: scratch(2048) + wred(32) + small(128)
#define SCRATCH_OFF 0
#define WRED_OFF    2048
#define SMALL_OFF   2080
#define SM_TOTAL    2208

// small-region indices
#define SM_VSUM 0   // [2][16] running sum of v's
#define SM_Z    64  // Z0, Z1

__device__ __forceinline__ void block_reduce2_sum(float v0, float v1, float* wred,
                                                  float* small, int tid) {
    const unsigned FULL = 0xffffffffu;
    #pragma unroll
    for (int off = 16; off > 0; off >>= 1) {
        v0 += __shfl_xor_sync(FULL, v0, off);
        v1 += __shfl_xor_sync(FULL, v1, off);
    }
    int lane = tid & 31, wid = tid >> 5;
    if (lane == 0) { wred[wid * 2] = v0; wred[wid * 2 + 1] = v1; }
    __syncthreads();
    if (tid == 0) {
        float a0 = wred[0], a1 = wred[1];
        #pragma unroll
        for (int w = 1; w < TPB / 32; w++) {
            a0 += wred[w * 2];
            a1 += wred[w * 2 + 1];
        }
        small[SM_Z] = a0; small[SM_Z + 1] = a1;
    }
    __syncthreads();
}

// Reduce 128-group partials -> s[2][16], scale by invZ, squash, accumulate Vsum.
__device__ __forceinline__ void finish_step(float* scratch, float* small, int tid,
                                            float invZ0, float invZ1,
                                            bool write_out, float* out_v,
                                            int b_base, int o) {
    if (tid < 32) {
        int b = tid >> 4, g = tid & 15;
        float s = 0.f;
        const float* sc = scratch + (b * 64) * 16 + g;
        #pragma unroll 8
        for (int grp = 0; grp < 64; grp++) s += sc[grp * 16];
        s *= (b ? invZ1 : invZ0);
        // squash: v = s * n / (n^2 + 1), n = ||s|| over g (16 lanes)
        float sq = s * s;
        #pragma unroll
        for (int off = 8; off > 0; off >>= 1)
            sq += __shfl_xor_sync(0xffffffffu, sq, off);   // stays in 16-lane half
        float n = sqrtf(sq);
        float fac = n / (sq + 1.0f);
        float v = s * fac;
        small[SM_VSUM + tid] += v;
        if (write_out)
            out_v[((b_base + b) * O_DIM + o) * G_DIM + g] = v;
    }
    __syncthreads();
}

__global__ void __launch_bounds__(TPB, 1)
caps_kernel(const float* __restrict__ x, const float* __restrict__ W,
            float* __restrict__ out_v, float* __restrict__ out_u) {
    __shared__ float sm[SM_TOTAL];
    float* scratch = sm + SCRATCH_OFF;   // 2048 floats (128 groups x 16)
    float* wred    = sm + WRED_OFF;      // 32 floats
    float* small   = sm + SMALL_OFF;     // 128 floats

    const int tid = threadIdx.x;
    const int o = blockIdx.y;
    const int b_base = blockIdx.x * BTILE;

    const int lane = tid & 31;
    const int warp = tid >> 5;
    const int octw = lane >> 3;          // octet within warp 0..3
    const int l    = lane & 7;           // lane within octet
    const int q    = l & 3;              // g-slice [4q,4q+4)
    const int half = l >> 2;             // 0 -> keeps b0, 1 -> keeps b1; f-parity
    const int ot   = warp * 4 + octw;    // global octet 0..63
    const int group = half * 64 + ot;    // scratch partition (b-major)
    const int i_base = warp * 72 + octw; // k=0 i for this octet

    if (tid < 32) small[SM_VSUM + tid] = 0.f;
    __syncthreads();

    const unsigned FULL = 0xffffffffu;
    float4 u[IPT];

    // ---- phase 1: compute u into registers, store to gmem, uniform-weight sums ----
    {
        float a0 = 0.f, a1 = 0.f, a2 = 0.f, a3 = 0.f;
        // induction pointers (64-bit math hoisted; constant strides inside loop)
        const float4* wb = reinterpret_cast<const float4*>(W) +
            (size_t)(i_base * O_DIM + o) * 32 + l;
        const float* x0r = x + ((size_t)b_base * I_DIM + i_base) * F_DIM + half;
        const float* x1r = x0r + (size_t)I_DIM * F_DIM;
        float4* og = reinterpret_cast<float4*>(out_u) +
            (((size_t)(b_base + half) * I_DIM + i_base) * O_DIM + o) * 4 + q;

        #pragma unroll 2
        for (int k = 0; k < IPT; k++) {
            // this lane's f-set {half,2+half,4+half,6+half}: stride-2 scalar loads
            float X00 = x0r[0], X01 = x0r[2], X02 = x0r[4], X03 = x0r[6];
            float X10 = x1r[0], X11 = x1r[2], X12 = x1r[4], X13 = x1r[6];

            float4 acc0 = make_float4(0.f, 0.f, 0.f, 0.f);
            float4 acc1 = make_float4(0.f, 0.f, 0.f, 0.f);
            {
                float4 w = wb[0];                  // f = 0+half
                acc0.x = fmaf(X00, w.x, acc0.x); acc0.y = fmaf(X00, w.y, acc0.y);
                acc0.z = fmaf(X00, w.z, acc0.z); acc0.w = fmaf(X00, w.w, acc0.w);
                acc1.x = fmaf(X10, w.x, acc1.x); acc1.y = fmaf(X10, w.y, acc1.y);
                acc1.z = fmaf(X10, w.z, acc1.z); acc1.w = fmaf(X10, w.w, acc1.w);
            }
            {
                float4 w = wb[8];                  // f = 2+half
                acc0.x = fmaf(X01, w.x, acc0.x); acc0.y = fmaf(X01, w.y, acc0.y);
                acc0.z = fmaf(X01, w.z, acc0.z); acc0.w = fmaf(X01, w.w, acc0.w);
                acc1.x = fmaf(X11, w.x, acc1.x); acc1.y = fmaf(X11, w.y, acc1.y);
                acc1.z = fmaf(X11, w.z, acc1.z); acc1.w = fmaf(X11, w.w, acc1.w);
            }
            {
                float4 w = wb[16];                 // f = 4+half
                acc0.x = fmaf(X02, w.x, acc0.x); acc0.y = fmaf(X02, w.y, acc0.y);
                acc0.z = fmaf(X02, w.z, acc0.z); acc0.w = fmaf(X02, w.w, acc0.w);
                acc1.x = fmaf(X12, w.x, acc1.x); acc1.y = fmaf(X12, w.y, acc1.y);
                acc1.z = fmaf(X12, w.z, acc1.z); acc1.w = fmaf(X12, w.w, acc1.w);
            }
            {
                float4 w = wb[24];                 // f = 6+half
                acc0.x = fmaf(X03, w.x, acc0.x); acc0.y = fmaf(X03, w.y, acc0.y);
                acc0.z = fmaf(X03, w.z, acc0.z); acc0.w = fmaf(X03, w.w, acc0.w);
                acc1.x = fmaf(X13, w.x, acc1.x); acc1.y = fmaf(X13, w.y, acc1.y);
                acc1.z = fmaf(X13, w.z, acc1.z); acc1.w = fmaf(X13, w.w, acc1.w);
            }
            // exchange complementary f-half: lane keeps b = half.
            float4 send = half ? acc0 : acc1;
            send.x = __shfl_xor_sync(FULL, send.x, 4);
            send.y = __shfl_xor_sync(FULL, send.y, 4);
            send.z = __shfl_xor_sync(FULL, send.z, 4);
            send.w = __shfl_xor_sync(FULL, send.w, 4);
            float4 mine = half ? acc1 : acc0;
            float4 r = make_float4(mine.x + send.x, mine.y + send.y,
                                   mine.z + send.z, mine.w + send.w);
            u[k] = r;
            *og = r;
            a0 += r.x; a1 += r.y; a2 += r.z; a3 += r.w;

            wb  += W_STRIDE_V4;
            x0r += X_STRIDE_F;
            x1r += X_STRIDE_F;
            og  += U_STRIDE_V4;
        }
        float* scr = scratch + group * 16 + q * 4;
        scr[0] = a0; scr[1] = a1; scr[2] = a2; scr[3] = a3;
        __syncthreads();
    }

    // step 1: uniform coefficients -> mean over i
    finish_step(scratch, small, tid, 1.0f / I_DIM, 1.0f / I_DIM,
                false, out_v, b_base, o);

    // ---- routing steps 2 and 3 (all register-resident) ----
    #pragma unroll 1
    for (int step = 1; step < 3; step++) {
        // per-i dot with Vsum (quad-completed), exp, partial Z
        float4 V = reinterpret_cast<const float4*>(small + SM_VSUM + half * G_DIM)[q];
        float e[IPT];
        float pz = 0.f;
        #pragma unroll
        for (int k = 0; k < IPT; k++) {
            float d = u[k].x * V.x + u[k].y * V.y + u[k].z * V.z + u[k].w * V.w;
            d += __shfl_xor_sync(FULL, d, 1);
            d += __shfl_xor_sync(FULL, d, 2);     // full 16-g dot within quad
            float ev = __expf(d);                 // |d| <~ 25, safe in fp32
            e[k] = ev;
            pz += ev;
        }
        // Z per b (each (b,i) counted by its 4 quad lanes -> x4)
        block_reduce2_sum(half ? 0.f : pz, half ? pz : 0.f, wred, small, tid);
        float invZ0 = 4.0f / small[SM_Z];
        float invZ1 = 4.0f / small[SM_Z + 1];

        // weighted accumulation from registers
        float a0 = 0.f, a1 = 0.f, a2 = 0.f, a3 = 0.f;
        #pragma unroll
        for (int k = 0; k < IPT; k++) {
            float ev = e[k];
            a0 = fmaf(ev, u[k].x, a0);
            a1 = fmaf(ev, u[k].y, a1);
            a2 = fmaf(ev, u[k].z, a2);
            a3 = fmaf(ev, u[k].w, a3);
        }
        float* scr = scratch + group * 16 + q * 4;
        scr[0] = a0; scr[1] = a1; scr[2] = a2; scr[3] = a3;
        __syncthreads();

        finish_step(scratch, small, tid, invZ0, invZ1,
                    (step == 2), out_v, b_base, o);
    }
}

extern "C" void kernel_launch(void* const* d_in, const int* in_sizes, int n_in,
                              void* d_out, int out_size) {
    const float* x = (const float*)d_in[0];   // [256,1152,8]
    const float* W = (const float*)d_in[1];   // [1152,10,8,16]
    float* out = (float*)d_out;
    float* out_v = out;                         // [256,10,16] = 40960
    float* out_u = out + B_DIM * O_DIM * G_DIM; // [256,1152,10,16]

    dim3 grid(B_DIM / BTILE, O_DIM);
    caps_kernel<<<grid, TPB>>>(x, W, out_v, out_u);
}